// round 6
// baseline (speedup 1.0000x reference)
#include <cuda_runtime.h>
#include <cuda_bf16.h>
#include <cstdint>

// Problem constants
#define BB 8        // half-batch
#define NN 1024     // sequence length
#define EE 64       // embedding channels
#define CC 512      // CH
#define DD 4096     // BB * CC
#define EPS_LN 1e-5f

// ---------------- scratch (__device__ globals) ----------------------------
__device__ float g_qT[BB][CC][NN];        // qT[b][c][n]
__device__ float g_kbank[NN][DD];         // k_bank[n][b*512+c]
__device__ float g_vbank[NN][DD];
__device__ float g_scores[BB][CC][DD];    // raw scores, then exp()
__device__ float g_ctx[BB][CC][NN];
__device__ float g_sum[BB];
__device__ float g_sumsq[BB];
__device__ float g_rowinv[BB][CC];

// ---------------- helpers -------------------------------------------------
__device__ __forceinline__ uint32_t tf32u(float x) {
    uint32_t u;
    asm("cvt.rna.tf32.f32 %0, %1;" : "=r"(u) : "f"(x));
    return u;
}

__device__ __forceinline__ void mma_tf32(float c[4],
    uint32_t a0, uint32_t a1, uint32_t a2, uint32_t a3,
    uint32_t b0, uint32_t b1)
{
    asm volatile(
        "mma.sync.aligned.m16n8k8.row.col.f32.tf32.tf32.f32 "
        "{%0,%1,%2,%3},{%4,%5,%6,%7},{%8,%9},{%0,%1,%2,%3};"
        : "+f"(c[0]), "+f"(c[1]), "+f"(c[2]), "+f"(c[3])
        : "r"(a0), "r"(a1), "r"(a2), "r"(a3), "r"(b0), "r"(b1));
}

// swizzled k-major smem layout (validated in round 2)
#define SWIDX(k, m) ((k) * 136 + ((m) ^ ((((k) >> 2) & 3) << 3)))

// ---------------- init ----------------------------------------------------
__global__ void k_init() {
    int t = threadIdx.x;
    if (t < BB) { g_sum[t] = 0.f; g_sumsq[t] = 0.f; }
}

// ---------------- kernel 1: q/k/v projections (round-2 verbatim) ----------
__global__ __launch_bounds__(256) void k_proj(
    const float* __restrict__ emb, const float* __restrict__ Wq,
    const float* __restrict__ Wk,  const float* __restrict__ Wv)
{
    __shared__ float embS[64][68];
    __shared__ float WS[64][68];

    int ntile = blockIdx.x, ctile = blockIdx.y, bz = blockIdx.z;
    int b = bz / 3, m = bz % 3;
    const float* W  = (m == 0) ? Wq : ((m == 1) ? Wk : Wv);
    const float* eb = emb + (size_t)((m == 0) ? (BB + b) : b) * NN * EE;
    int n0 = ntile * 64, c0 = ctile * 64;
    int t = threadIdx.x;

    #pragma unroll
    for (int r = 0; r < 4; r++) {
        int chunk = t + 256 * r;
        int row = chunk >> 4;
        int col = (chunk & 15) * 4;
        *(float4*)&embS[row][col] = *(const float4*)&eb[(size_t)(n0 + row) * EE + col];
        *(float4*)&WS[row][col]   = *(const float4*)&W[(size_t)(c0 + row) * EE + col];
    }
    __syncthreads();

    int ty = t >> 4, tx = t & 15;
    float acc[4][4] = {};
    #pragma unroll 16
    for (int e = 0; e < 64; e++) {
        float a[4], bv[4];
        #pragma unroll
        for (int i = 0; i < 4; i++) a[i]  = embS[ty + 16 * i][e];
        #pragma unroll
        for (int j = 0; j < 4; j++) bv[j] = WS[tx + 16 * j][e];
        #pragma unroll
        for (int i = 0; i < 4; i++)
            #pragma unroll
            for (int j = 0; j < 4; j++) acc[i][j] += a[i] * bv[j];
    }

    if (m == 0) {
        #pragma unroll
        for (int i = 0; i < 4; i++)
            #pragma unroll
            for (int j = 0; j < 4; j++)
                g_qT[b][c0 + tx + 16 * j][n0 + ty + 16 * i] = acc[i][j];
    } else {
        float (*bank)[DD] = (m == 1) ? g_kbank : g_vbank;
        #pragma unroll
        for (int i = 0; i < 4; i++)
            #pragma unroll
            for (int j = 0; j < 4; j++)
                bank[n0 + ty + 16 * i][b * CC + c0 + tx + 16 * j] = acc[i][j];
    }
}

// ---------------- kernel 2: scores GEMM (round-2 + reg-prefetch pipeline) --
__global__ __launch_bounds__(256, 2) void k_scores()
{
    __shared__ float As[2][16 * 136];
    __shared__ float Bs[2][16 * 136];
    __shared__ float red[256];

    int m0 = blockIdx.x * 128, n0 = blockIdx.y * 128, b = blockIdx.z;
    int t = threadIdx.x, lane = t & 31, warp = t >> 5;
    int wm = (warp & 1) * 64, wn = (warp >> 1) * 32;

    // staging geometry (round-2)
    const int arow0 = t >> 2,  akc0 = (t & 3) * 4;        // rep r: ch = t + 256r
    const int brow0 = t >> 5,  bcol0 = (t & 31) * 4;

    float4 fa[2], fb[2];
    auto ldg = [&](int k0) {
        #pragma unroll
        for (int r = 0; r < 2; r++) {
            int arow = arow0 + 64 * r;                    // (t+256r)>>2
            fa[r] = *(const float4*)&g_qT[b][m0 + arow][k0 + akc0];
            int brow = brow0 + 8 * r;                     // (t+256r)>>5
            fb[r] = *(const float4*)&g_kbank[k0 + brow][n0 + bcol0];
        }
    };
    auto sts = [&](int buf) {
        #pragma unroll
        for (int r = 0; r < 2; r++) {
            int arow = arow0 + 64 * r;
            As[buf][SWIDX(akc0 + 0, arow)] = __uint_as_float(tf32u(fa[r].x));
            As[buf][SWIDX(akc0 + 1, arow)] = __uint_as_float(tf32u(fa[r].y));
            As[buf][SWIDX(akc0 + 2, arow)] = __uint_as_float(tf32u(fa[r].z));
            As[buf][SWIDX(akc0 + 3, arow)] = __uint_as_float(tf32u(fa[r].w));
            int brow = brow0 + 8 * r;
            float4 cb;
            cb.x = __uint_as_float(tf32u(fb[r].x));
            cb.y = __uint_as_float(tf32u(fb[r].y));
            cb.z = __uint_as_float(tf32u(fb[r].z));
            cb.w = __uint_as_float(tf32u(fb[r].w));
            *(float4*)&Bs[buf][brow * 136 + bcol0] = cb;
        }
    };

    float acc[4][4][4] = {};
    constexpr int T = NN / 16;
    ldg(0);

    for (int it = 0; it < T; it++) {
        int cur = it & 1;
        sts(cur);
        if (it + 1 < T) ldg((it + 1) * 16);
        __syncthreads();

        const float* A_ = As[cur];
        const float* B_ = Bs[cur];
        #pragma unroll
        for (int ks = 0; ks < 16; ks += 8) {
            uint32_t af[4][4], bf[4][2];
            int kk = ks + (lane & 3);
            #pragma unroll
            for (int mi = 0; mi < 4; mi++) {
                int m = wm + mi * 16 + (lane >> 2);
                af[mi][0] = __float_as_uint(A_[SWIDX(kk, m)]);
                af[mi][1] = __float_as_uint(A_[SWIDX(kk, m + 8)]);
                af[mi][2] = __float_as_uint(A_[SWIDX(kk + 4, m)]);
                af[mi][3] = __float_as_uint(A_[SWIDX(kk + 4, m + 8)]);
            }
            #pragma unroll
            for (int ni = 0; ni < 4; ni++) {
                int n = wn + ni * 8 + (lane >> 2);
                bf[ni][0] = __float_as_uint(B_[kk * 136 + n]);
                bf[ni][1] = __float_as_uint(B_[(kk + 4) * 136 + n]);
            }
            #pragma unroll
            for (int mi = 0; mi < 4; mi++)
                #pragma unroll
                for (int ni = 0; ni < 4; ni++)
                    mma_tf32(acc[mi][ni], af[mi][0], af[mi][1], af[mi][2], af[mi][3],
                             bf[ni][0], bf[ni][1]);
        }
    }

    // epilogue (round-2 verbatim)
    float ls = 0.f, lq = 0.f;
    #pragma unroll
    for (int mi = 0; mi < 4; mi++)
        #pragma unroll
        for (int ni = 0; ni < 4; ni++)
            #pragma unroll
            for (int h = 0; h < 2; h++) {
                int row = m0 + wm + mi * 16 + (lane >> 2) + h * 8;
                int col = n0 + wn + ni * 8 + 2 * (lane & 3);
                float v0 = acc[mi][ni][2 * h + 0];
                float v1 = acc[mi][ni][2 * h + 1];
                float2 st; st.x = v0; st.y = v1;
                *(float2*)&g_scores[b][row][col] = st;
                ls += v0 + v1;
                lq += v0 * v0 + v1 * v1;
            }

    __syncthreads();
    red[t] = ls; __syncthreads();
    for (int s = 128; s > 0; s >>= 1) { if (t < s) red[t] += red[t + s]; __syncthreads(); }
    if (t == 0) atomicAdd(&g_sum[b], red[0]);
    __syncthreads();
    red[t] = lq; __syncthreads();
    for (int s = 128; s > 0; s >>= 1) { if (t < s) red[t] += red[t + s]; __syncthreads(); }
    if (t == 0) atomicAdd(&g_sumsq[b], red[0]);
}

// ---------------- kernel 3: LN + exp + row-sum (round-2 verbatim) ---------
__global__ __launch_bounds__(256) void k_softmax()
{
    int c = blockIdx.x, b = blockIdx.y;
    int t = threadIdx.x;
    __shared__ float red[256];

    const float invCD = 1.0f / ((float)CC * (float)DD);
    float mean = g_sum[b] * invCD;
    float var  = g_sumsq[b] * invCD - mean * mean;
    float rstd = rsqrtf(var + EPS_LN);

    float* row = &g_scores[b][c][0];
    float ls = 0.f;
    #pragma unroll
    for (int r = 0; r < 4; r++) {
        int idx = (t + 256 * r) * 4;
        float4 v = *(float4*)&row[idx];
        v.x = __expf((v.x - mean) * rstd);
        v.y = __expf((v.y - mean) * rstd);
        v.z = __expf((v.z - mean) * rstd);
        v.w = __expf((v.w - mean) * rstd);
        *(float4*)&row[idx] = v;
        ls += v.x + v.y + v.z + v.w;
    }
    red[t] = ls; __syncthreads();
    for (int s = 128; s > 0; s >>= 1) { if (t < s) red[t] += red[t + s]; __syncthreads(); }
    if (t == 0) g_rowinv[b][c] = 1.0f / red[0];
}

// ---------------- kernel 4: ctx GEMM (round-2 + reg-prefetch pipeline) ----
__global__ __launch_bounds__(256, 2) void k_ctx()
{
    __shared__ float As[2][16 * 136];
    __shared__ float Bs[2][128 * 17];

    int m0 = blockIdx.x * 128, n0 = blockIdx.y * 128, b = blockIdx.z;
    int t = threadIdx.x, lane = t & 31, warp = t >> 5;
    int wm = (warp & 1) * 64, wn = (warp >> 1) * 32;

    const int row0 = t >> 2, kc0 = (t & 3) * 4;

    float4 fa[2], fb[2];
    auto ldg = [&](int k0) {
        #pragma unroll
        for (int r = 0; r < 2; r++) {
            int row = row0 + 64 * r;
            fa[r] = *(const float4*)&g_scores[b][m0 + row][k0 + kc0];
            fb[r] = *(const float4*)&g_vbank[n0 + row][k0 + kc0];
        }
    };
    auto sts = [&](int buf) {
        #pragma unroll
        for (int r = 0; r < 2; r++) {
            int row = row0 + 64 * r;
            As[buf][SWIDX(kc0 + 0, row)] = __uint_as_float(tf32u(fa[r].x));
            As[buf][SWIDX(kc0 + 1, row)] = __uint_as_float(tf32u(fa[r].y));
            As[buf][SWIDX(kc0 + 2, row)] = __uint_as_float(tf32u(fa[r].z));
            As[buf][SWIDX(kc0 + 3, row)] = __uint_as_float(tf32u(fa[r].w));
            Bs[buf][row * 17 + kc0 + 0] = __uint_as_float(tf32u(fb[r].x));
            Bs[buf][row * 17 + kc0 + 1] = __uint_as_float(tf32u(fb[r].y));
            Bs[buf][row * 17 + kc0 + 2] = __uint_as_float(tf32u(fb[r].z));
            Bs[buf][row * 17 + kc0 + 3] = __uint_as_float(tf32u(fb[r].w));
        }
    };

    float acc[4][4][4] = {};
    constexpr int T = DD / 16;
    ldg(0);

    for (int it = 0; it < T; it++) {
        int cur = it & 1;
        sts(cur);
        if (it + 1 < T) ldg((it + 1) * 16);
        __syncthreads();

        const float* A_ = As[cur];
        const float* B_ = Bs[cur];
        #pragma unroll
        for (int ks = 0; ks < 16; ks += 8) {
            uint32_t af[4][4], bf[4][2];
            int kk = ks + (lane & 3);
            #pragma unroll
            for (int mi = 0; mi < 4; mi++) {
                int m = wm + mi * 16 + (lane >> 2);
                af[mi][0] = __float_as_uint(A_[SWIDX(kk, m)]);
                af[mi][1] = __float_as_uint(A_[SWIDX(kk, m + 8)]);
                af[mi][2] = __float_as_uint(A_[SWIDX(kk + 4, m)]);
                af[mi][3] = __float_as_uint(A_[SWIDX(kk + 4, m + 8)]);
            }
            #pragma unroll
            for (int ni = 0; ni < 4; ni++) {
                int n = wn + ni * 8 + (lane >> 2);
                bf[ni][0] = __float_as_uint(B_[n * 17 + kk]);
                bf[ni][1] = __float_as_uint(B_[n * 17 + kk + 4]);
            }
            #pragma unroll
            for (int mi = 0; mi < 4; mi++)
                #pragma unroll
                for (int ni = 0; ni < 4; ni++)
                    mma_tf32(acc[mi][ni], af[mi][0], af[mi][1], af[mi][2], af[mi][3],
                             bf[ni][0], bf[ni][1]);
        }
    }

    #pragma unroll
    for (int mi = 0; mi < 4; mi++)
        #pragma unroll
        for (int ni = 0; ni < 4; ni++)
            #pragma unroll
            for (int h = 0; h < 2; h++) {
                int row = m0 + wm + mi * 16 + (lane >> 2) + h * 8;
                int col = n0 + wn + ni * 8 + 2 * (lane & 3);
                float inv = g_rowinv[b][row];
                float2 st;
                st.x = acc[mi][ni][2 * h + 0] * inv;
                st.y = acc[mi][ni][2 * h + 1] * inv;
                *(float2*)&g_ctx[b][row][col] = st;
            }
}

// ---------------- kernel 5: output projection (round-2 verbatim) ----------
__global__ __launch_bounds__(256) void k_out(
    const float* __restrict__ Wo, float* __restrict__ out)
{
    __shared__ float ctxS[16][68];
    __shared__ float WoS[16][68];

    int n0 = blockIdx.x * 64;
    int b  = blockIdx.y;
    int t = threadIdx.x, ty = t >> 4, tx = t & 15;

    float acc[4][4] = {};
    for (int c0 = 0; c0 < CC; c0 += 16) {
        {
            int row = t >> 4, col = (t & 15) * 4;
            *(float4*)&ctxS[row][col] = *(const float4*)&g_ctx[b][c0 + row][n0 + col];
            int e = t >> 2, cc4 = (t & 3) * 4;
            float4 w = *(const float4*)&Wo[(size_t)e * CC + c0 + cc4];
            WoS[cc4 + 0][e] = w.x; WoS[cc4 + 1][e] = w.y;
            WoS[cc4 + 2][e] = w.z; WoS[cc4 + 3][e] = w.w;
        }
        __syncthreads();
        #pragma unroll
        for (int cc = 0; cc < 16; cc++) {
            float a[4], bv[4];
            #pragma unroll
            for (int i = 0; i < 4; i++) a[i]  = ctxS[cc][ty + 16 * i];
            #pragma unroll
            for (int j = 0; j < 4; j++) bv[j] = WoS[cc][tx + 16 * j];
            #pragma unroll
            for (int i = 0; i < 4; i++)
                #pragma unroll
                for (int j = 0; j < 4; j++) acc[i][j] += a[i] * bv[j];
        }
        __syncthreads();
    }
    #pragma unroll
    for (int i = 0; i < 4; i++)
        #pragma unroll
        for (int j = 0; j < 4; j++)
            out[((size_t)b * NN + n0 + ty + 16 * i) * EE + tx + 16 * j] = acc[i][j];
}

// ---------------- launch ---------------------------------------------------
extern "C" void kernel_launch(void* const* d_in, const int* in_sizes, int n_in,
                              void* d_out, int out_size)
{
    const float* emb = (const float*)d_in[0];
    const float* Wq  = (const float*)d_in[1];
    const float* Wk  = (const float*)d_in[2];
    const float* Wv  = (const float*)d_in[3];
    const float* Wo  = (const float*)d_in[4];
    float* out = (float*)d_out;

    k_init<<<1, 32>>>();

    dim3 g1(16, 8, 24);
    k_proj<<<g1, 256>>>(emb, Wq, Wk, Wv);

    dim3 g2(4, 32, 8);           // 512/128 x 4096/128 x B
    k_scores<<<g2, 256>>>();

    dim3 g3(512, 8);
    k_softmax<<<g3, 256>>>();

    dim3 g4(4, 8, 8);            // 512/128 x 1024/128 x B
    k_ctx<<<g4, 256>>>();

    dim3 g5(16, 8);
    k_out<<<g5, 256>>>(Wo, out);
}

// round 8
// speedup vs baseline: 1.8544x; 1.8544x over previous
#include <cuda_runtime.h>
#include <cuda_fp16.h>
#include <cstdint>

// Problem constants
#define BB 8        // half-batch
#define NN 1024     // sequence length
#define EE 64       // embedding channels
#define CC 512      // CH
#define DD 4096     // BB * CC
#define EPS_LN 1e-5f

// ---------------- scratch (__device__ globals) ----------------------------
__device__ __half g_qTh[BB][CC][NN];      // A of scores: [c][n], k=n contig
__device__ __half g_kTh[DD][NN];          // B of scores: [d][n], k=n contig
__device__ __half g_vh[NN][DD];           // B of ctx:    [n][d], k=d contig
__device__ __half g_expS[BB][CC][DD];     // A of ctx: exp(LN(scores)), half
__device__ float  g_scores[BB][CC][DD];   // raw scores fp32 (for LN stats)
__device__ float  g_ctx[BB][CC][NN];
__device__ float  g_sum[BB];
__device__ float  g_sumsq[BB];
__device__ float  g_rowinv[BB][CC];

// ---------------- helpers -------------------------------------------------
__device__ __forceinline__ void mma_f16(float c[4],
    uint32_t a0, uint32_t a1, uint32_t a2, uint32_t a3,
    uint32_t b0, uint32_t b1)
{
    asm volatile(
        "mma.sync.aligned.m16n8k16.row.col.f32.f16.f16.f32 "
        "{%0,%1,%2,%3},{%4,%5,%6,%7},{%8,%9},{%0,%1,%2,%3};"
        : "+f"(c[0]), "+f"(c[1]), "+f"(c[2]), "+f"(c[3])
        : "r"(a0), "r"(a1), "r"(a2), "r"(a3), "r"(b0), "r"(b1));
}

// padded half rows: 40 halfs (80B) per 32-half row -> conflict-free stores+loads
__device__ __forceinline__ uint32_t lds32(const __half* base, int row, int kk) {
    return *(const uint32_t*)((const char*)base + row * 80 + kk * 2);
}

// ---------------- init ----------------------------------------------------
__global__ void k_init() {
    int t = threadIdx.x;
    if (t < BB) { g_sum[t] = 0.f; g_sumsq[t] = 0.f; }
}

// ---------------- kernel 1: q/k/v projections ------------------------------
__global__ __launch_bounds__(256) void k_proj(
    const float* __restrict__ emb, const float* __restrict__ Wq,
    const float* __restrict__ Wk,  const float* __restrict__ Wv)
{
    __shared__ float embS[64][68];
    __shared__ float WS[64][68];

    int ntile = blockIdx.x, ctile = blockIdx.y, bz = blockIdx.z;
    int b = bz / 3, m = bz % 3;
    const float* W  = (m == 0) ? Wq : ((m == 1) ? Wk : Wv);
    const float* eb = emb + (size_t)((m == 0) ? (BB + b) : b) * NN * EE;
    int n0 = ntile * 64, c0 = ctile * 64;
    int t = threadIdx.x;

    #pragma unroll
    for (int r = 0; r < 4; r++) {
        int chunk = t + 256 * r;
        int row = chunk >> 4;
        int col = (chunk & 15) * 4;
        *(float4*)&embS[row][col] = *(const float4*)&eb[(size_t)(n0 + row) * EE + col];
        *(float4*)&WS[row][col]   = *(const float4*)&W[(size_t)(c0 + row) * EE + col];
    }
    __syncthreads();

    int ty = t >> 4, tx = t & 15;
    float acc[4][4] = {};
    #pragma unroll 16
    for (int e = 0; e < 64; e++) {
        float a[4], bv[4];
        #pragma unroll
        for (int i = 0; i < 4; i++) a[i]  = embS[ty + 16 * i][e];
        #pragma unroll
        for (int j = 0; j < 4; j++) bv[j] = WS[tx + 16 * j][e];
        #pragma unroll
        for (int i = 0; i < 4; i++)
            #pragma unroll
            for (int j = 0; j < 4; j++) acc[i][j] += a[i] * bv[j];
    }

    if (m == 0) {
        #pragma unroll
        for (int i = 0; i < 4; i++)
            #pragma unroll
            for (int j = 0; j < 4; j++)
                g_qTh[b][c0 + tx + 16 * j][n0 + ty + 16 * i] = __float2half_rn(acc[i][j]);
    } else if (m == 1) {
        #pragma unroll
        for (int i = 0; i < 4; i++)
            #pragma unroll
            for (int j = 0; j < 4; j++)
                g_kTh[b * CC + c0 + tx + 16 * j][n0 + ty + 16 * i] = __float2half_rn(acc[i][j]);
    } else {
        #pragma unroll
        for (int i = 0; i < 4; i++)
            #pragma unroll
            for (int j = 0; j < 4; j++)
                g_vh[n0 + ty + 16 * i][b * CC + c0 + tx + 16 * j] = __float2half_rn(acc[i][j]);
    }
}

// ---------------- kernel 2: scores GEMM (fp16 mma, plain kernel) -----------
// S[b](512x4096) = qTh[b](512rows,k=n) @ kTh(4096rows,k=n)^T, fp32 accum.
__global__ __launch_bounds__(256, 2) void k_scores()
{
    __shared__ __align__(16) __half As[2][128 * 40];
    __shared__ __align__(16) __half Bs[2][128 * 40];
    __shared__ float red[256];

    const int m0 = blockIdx.x * 128, n0 = blockIdx.y * 128, b = blockIdx.z;
    const int t = threadIdx.x, lane = t & 31, warp = t >> 5;
    const int wm = (warp & 1) * 64, wn = (warp >> 1) * 32;

    const __half* A  = &g_qTh[b][m0][0];
    const __half* Bp = &g_kTh[n0][0];

    const int row0 = t >> 2;            // 0..63 (+64 for rep 1)
    const int c16  = t & 3;             // 16B chunk (8 halfs) within 64B row

    uint4 fa[2], fb[2];
    auto ldg = [&](int k0) {
        #pragma unroll
        for (int r = 0; r < 2; r++) {
            int row = row0 + 64 * r;
            fa[r] = *(const uint4*)(A  + (size_t)row * NN + k0 + c16 * 8);
            fb[r] = *(const uint4*)(Bp + (size_t)row * NN + k0 + c16 * 8);
        }
    };
    auto sts = [&](int buf) {
        #pragma unroll
        for (int r = 0; r < 2; r++) {
            int row = row0 + 64 * r;
            *(uint4*)((char*)&As[buf][0] + row * 80 + c16 * 16) = fa[r];
            *(uint4*)((char*)&Bs[buf][0] + row * 80 + c16 * 16) = fb[r];
        }
    };

    float acc[4][4][4] = {};
    constexpr int T = NN / 32;
    ldg(0);

    for (int it = 0; it < T; it++) {
        int cur = it & 1;
        sts(cur);
        if (it + 1 < T) ldg((it + 1) * 32);
        __syncthreads();

        const __half* A_ = As[cur];
        const __half* B_ = Bs[cur];
        #pragma unroll
        for (int ks = 0; ks < 32; ks += 16) {
            int kk = ks + (lane & 3) * 2;
            uint32_t af[4][4], bf[4][2];
            #pragma unroll
            for (int mi = 0; mi < 4; mi++) {
                int m = wm + mi * 16 + (lane >> 2);
                af[mi][0] = lds32(A_, m,     kk);
                af[mi][1] = lds32(A_, m + 8, kk);
                af[mi][2] = lds32(A_, m,     kk + 8);
                af[mi][3] = lds32(A_, m + 8, kk + 8);
            }
            #pragma unroll
            for (int ni = 0; ni < 4; ni++) {
                int n = wn + ni * 8 + (lane >> 2);
                bf[ni][0] = lds32(B_, n, kk);
                bf[ni][1] = lds32(B_, n, kk + 8);
            }
            #pragma unroll
            for (int mi = 0; mi < 4; mi++)
                #pragma unroll
                for (int ni = 0; ni < 4; ni++)
                    mma_f16(acc[mi][ni], af[mi][0], af[mi][1], af[mi][2], af[mi][3],
                            bf[ni][0], bf[ni][1]);
        }
    }

    float ls = 0.f, lq = 0.f;
    #pragma unroll
    for (int mi = 0; mi < 4; mi++)
        #pragma unroll
        for (int ni = 0; ni < 4; ni++)
            #pragma unroll
            for (int h = 0; h < 2; h++) {
                int row = m0 + wm + mi * 16 + (lane >> 2) + h * 8;
                int col = n0 + wn + ni * 8 + 2 * (lane & 3);
                float v0 = acc[mi][ni][2 * h + 0];
                float v1 = acc[mi][ni][2 * h + 1];
                float2 st; st.x = v0; st.y = v1;
                *(float2*)&g_scores[b][row][col] = st;
                ls += v0 + v1;
                lq += v0 * v0 + v1 * v1;
            }

    __syncthreads();
    red[t] = ls; __syncthreads();
    for (int s = 128; s > 0; s >>= 1) { if (t < s) red[t] += red[t + s]; __syncthreads(); }
    if (t == 0) atomicAdd(&g_sum[b], red[0]);
    __syncthreads();
    red[t] = lq; __syncthreads();
    for (int s = 128; s > 0; s >>= 1) { if (t < s) red[t] += red[t + s]; __syncthreads(); }
    if (t == 0) atomicAdd(&g_sumsq[b], red[0]);
}

// ---------------- kernel 3: LN + exp -> half + row-sum ---------------------
__global__ __launch_bounds__(256) void k_softmax()
{
    int c = blockIdx.x, b = blockIdx.y;
    int t = threadIdx.x;
    __shared__ float red[256];

    const float invCD = 1.0f / ((float)CC * (float)DD);
    float mean = g_sum[b] * invCD;
    float var  = g_sumsq[b] * invCD - mean * mean;
    float rstd = rsqrtf(var + EPS_LN);

    const float* row = &g_scores[b][c][0];
    __half* erow = &g_expS[b][c][0];
    float ls = 0.f;
    #pragma unroll
    for (int r = 0; r < 4; r++) {
        int idx = (t + 256 * r) * 4;
        float4 v = *(const float4*)&row[idx];
        v.x = __expf((v.x - mean) * rstd);
        v.y = __expf((v.y - mean) * rstd);
        v.z = __expf((v.z - mean) * rstd);
        v.w = __expf((v.w - mean) * rstd);
        ls += v.x + v.y + v.z + v.w;
        __half2 h0 = __floats2half2_rn(v.x, v.y);
        __half2 h1 = __floats2half2_rn(v.z, v.w);
        __half2* dst = (__half2*)&erow[idx];
        dst[0] = h0; dst[1] = h1;
    }
    red[t] = ls; __syncthreads();
    for (int s = 128; s > 0; s >>= 1) { if (t < s) red[t] += red[t + s]; __syncthreads(); }
    if (t == 0) g_rowinv[b][c] = 1.0f / red[0];
}

// ---------------- kernel 4: ctx GEMM (fp16 mma, plain kernel) --------------
// ctx[b](512x1024) = expS[b](512rows,k=d) @ vh(1024rows,k=d)^T * rowinv.
__global__ __launch_bounds__(256, 2) void k_ctx()
{
    __shared__ __align__(16) __half As[2][128 * 40];
    __shared__ __align__(16) __half Bs[2][128 * 40];

    const int m0 = blockIdx.x * 128, n0 = blockIdx.y * 128, b = blockIdx.z;
    const int t = threadIdx.x, lane = t & 31, warp = t >> 5;
    const int wm = (warp & 1) * 64, wn = (warp >> 1) * 32;

    const __half* A  = &g_expS[b][m0][0];
    const __half* Bp = &g_vh[n0][0];

    const int row0 = t >> 2;
    const int c16  = t & 3;

    uint4 fa[2], fb[2];
    auto ldg = [&](int k0) {
        #pragma unroll
        for (int r = 0; r < 2; r++) {
            int row = row0 + 64 * r;
            fa[r] = *(const uint4*)(A  + (size_t)row * DD + k0 + c16 * 8);
            fb[r] = *(const uint4*)(Bp + (size_t)row * DD + k0 + c16 * 8);
        }
    };
    auto sts = [&](int buf) {
        #pragma unroll
        for (int r = 0; r < 2; r++) {
            int row = row0 + 64 * r;
            *(uint4*)((char*)&As[buf][0] + row * 80 + c16 * 16) = fa[r];
            *(uint4*)((char*)&Bs[buf][0] + row * 80 + c16 * 16) = fb[r];
        }
    };

    float acc[4][4][4] = {};
    constexpr int T = DD / 32;
    ldg(0);

    for (int it = 0; it < T; it++) {
        int cur = it & 1;
        sts(cur);
        if (it + 1 < T) ldg((it + 1) * 32);
        __syncthreads();

        const __half* A_ = As[cur];
        const __half* B_ = Bs[cur];
        #pragma unroll
        for (int ks = 0; ks < 32; ks += 16) {
            int kk = ks + (lane & 3) * 2;
            uint32_t af[4][4], bf[4][2];
            #pragma unroll
            for (int mi = 0; mi < 4; mi++) {
                int m = wm + mi * 16 + (lane >> 2);
                af[mi][0] = lds32(A_, m,     kk);
                af[mi][1] = lds32(A_, m + 8, kk);
                af[mi][2] = lds32(A_, m,     kk + 8);
                af[mi][3] = lds32(A_, m + 8, kk + 8);
            }
            #pragma unroll
            for (int ni = 0; ni < 4; ni++) {
                int n = wn + ni * 8 + (lane >> 2);
                bf[ni][0] = lds32(B_, n, kk);
                bf[ni][1] = lds32(B_, n, kk + 8);
            }
            #pragma unroll
            for (int mi = 0; mi < 4; mi++)
                #pragma unroll
                for (int ni = 0; ni < 4; ni++)
                    mma_f16(acc[mi][ni], af[mi][0], af[mi][1], af[mi][2], af[mi][3],
                            bf[ni][0], bf[ni][1]);
        }
    }

    #pragma unroll
    for (int mi = 0; mi < 4; mi++)
        #pragma unroll
        for (int ni = 0; ni < 4; ni++)
            #pragma unroll
            for (int h = 0; h < 2; h++) {
                int row = m0 + wm + mi * 16 + (lane >> 2) + h * 8;
                int col = n0 + wn + ni * 8 + 2 * (lane & 3);
                float inv = g_rowinv[b][row];
                float2 st;
                st.x = acc[mi][ni][2 * h + 0] * inv;
                st.y = acc[mi][ni][2 * h + 1] * inv;
                *(float2*)&g_ctx[b][row][col] = st;
            }
}

// ---------------- kernel 5: output projection ------------------------------
__global__ __launch_bounds__(256) void k_out(
    const float* __restrict__ Wo, float* __restrict__ out)
{
    __shared__ float ctxS[16][68];
    __shared__ float WoS[16][68];

    int n0 = blockIdx.x * 64;
    int b  = blockIdx.y;
    int t = threadIdx.x, ty = t >> 4, tx = t & 15;

    float acc[4][4] = {};
    for (int c0 = 0; c0 < CC; c0 += 16) {
        {
            int row = t >> 4, col = (t & 15) * 4;
            *(float4*)&ctxS[row][col] = *(const float4*)&g_ctx[b][c0 + row][n0 + col];
            int e = t >> 2, cc4 = (t & 3) * 4;
            float4 w = *(const float4*)&Wo[(size_t)e * CC + c0 + cc4];
            WoS[cc4 + 0][e] = w.x; WoS[cc4 + 1][e] = w.y;
            WoS[cc4 + 2][e] = w.z; WoS[cc4 + 3][e] = w.w;
        }
        __syncthreads();
        #pragma unroll
        for (int cc = 0; cc < 16; cc++) {
            float a[4], bv[4];
            #pragma unroll
            for (int i = 0; i < 4; i++) a[i]  = ctxS[cc][ty + 16 * i];
            #pragma unroll
            for (int j = 0; j < 4; j++) bv[j] = WoS[cc][tx + 16 * j];
            #pragma unroll
            for (int i = 0; i < 4; i++)
                #pragma unroll
                for (int j = 0; j < 4; j++) acc[i][j] += a[i] * bv[j];
        }
        __syncthreads();
    }
    #pragma unroll
    for (int i = 0; i < 4; i++)
        #pragma unroll
        for (int j = 0; j < 4; j++)
            out[((size_t)b * NN + n0 + ty + 16 * i) * EE + tx + 16 * j] = acc[i][j];
}

// ---------------- launch ---------------------------------------------------
extern "C" void kernel_launch(void* const* d_in, const int* in_sizes, int n_in,
                              void* d_out, int out_size)
{
    const float* emb = (const float*)d_in[0];
    const float* Wq  = (const float*)d_in[1];
    const float* Wk  = (const float*)d_in[2];
    const float* Wv  = (const float*)d_in[3];
    const float* Wo  = (const float*)d_in[4];
    float* out = (float*)d_out;

    k_init<<<1, 32>>>();

    dim3 g1(16, 8, 24);
    k_proj<<<g1, 256>>>(emb, Wq, Wk, Wv);

    dim3 g2(CC / 128, DD / 128, BB);     // 4 x 32 x 8
    k_scores<<<g2, 256>>>();

    dim3 g3(512, 8);
    k_softmax<<<g3, 256>>>();

    dim3 g4(CC / 128, NN / 128, BB);     // 4 x 8 x 8
    k_ctx<<<g4, 256>>>();

    dim3 g5(16, 8);
    k_out<<<g5, 256>>>(Wo, out);
}

// round 9
// speedup vs baseline: 2.0703x; 1.1164x over previous
#include <cuda_runtime.h>
#include <cuda_fp16.h>
#include <cstdint>

// Problem constants
#define BB 8        // half-batch
#define NN 1024     // sequence length
#define EE 64       // embedding channels
#define CC 512      // CH
#define DD 4096     // BB * CC
#define EPS_LN 1e-5f

// ---------------- scratch (__device__ globals) ----------------------------
__device__ __half g_qTh[BB][CC][NN];      // A of scores: [c][n], k=n contig
__device__ __half g_kTh[DD][NN];          // B of scores: [d][n], k=n contig
__device__ __half g_vh[NN][DD];           // B of ctx:    [n][d], k=d contig
__device__ __half g_expS[BB][CC][DD];     // A of ctx: exp(LN(scores)), half
__device__ float  g_scores[BB][CC][DD];   // raw scores fp32 (for LN stats)
__device__ float  g_ctx[BB][CC][NN];      // fp32 [c][n]
__device__ float  g_sum[BB];
__device__ float  g_sumsq[BB];
__device__ float  g_rowinv[BB][CC];

// ---------------- helpers -------------------------------------------------
__device__ __forceinline__ void mma_f16(float c[4],
    uint32_t a0, uint32_t a1, uint32_t a2, uint32_t a3,
    uint32_t b0, uint32_t b1)
{
    asm volatile(
        "mma.sync.aligned.m16n8k16.row.col.f32.f16.f16.f32 "
        "{%0,%1,%2,%3},{%4,%5,%6,%7},{%8,%9},{%0,%1,%2,%3};"
        : "+f"(c[0]), "+f"(c[1]), "+f"(c[2]), "+f"(c[3])
        : "r"(a0), "r"(a1), "r"(a2), "r"(a3), "r"(b0), "r"(b1));
}

__device__ __forceinline__ void mma_tf32(float c[4],
    uint32_t a0, uint32_t a1, uint32_t a2, uint32_t a3,
    uint32_t b0, uint32_t b1)
{
    asm volatile(
        "mma.sync.aligned.m16n8k8.row.col.f32.tf32.tf32.f32 "
        "{%0,%1,%2,%3},{%4,%5,%6,%7},{%8,%9},{%0,%1,%2,%3};"
        : "+f"(c[0]), "+f"(c[1]), "+f"(c[2]), "+f"(c[3])
        : "r"(a0), "r"(a1), "r"(a2), "r"(a3), "r"(b0), "r"(b1));
}

__device__ __forceinline__ uint32_t tf32u(float x) {
    uint32_t u; asm("cvt.rna.tf32.f32 %0, %1;" : "=r"(u) : "f"(x)); return u;
}
__device__ __forceinline__ float tf32f(float x) { return __uint_as_float(tf32u(x)); }

// padded half rows: 40 halfs (80B) per 32-half row -> conflict-free stores+loads
__device__ __forceinline__ uint32_t lds32(const __half* base, int row, int kk) {
    return *(const uint32_t*)((const char*)base + row * 80 + kk * 2);
}

// ---------------- kernel 1: q/k/v projections ------------------------------
// q -> g_qTh[b][c][n], k -> g_kTh[b*CC+c][n] via smem transpose (coalesced
// 32B stores), v -> g_vh[n][b*CC+c] (naturally coalesced). First block also
// zeroes the LN stat accumulators (consumed only by the next kernel).
__global__ __launch_bounds__(256) void k_proj(
    const float* __restrict__ emb, const float* __restrict__ Wq,
    const float* __restrict__ Wk,  const float* __restrict__ Wv)
{
    __shared__ float embS[64][68];
    __shared__ float WS[64][68];
    __shared__ __half transS[64][72];   // 144B rows: 16B-aligned, conflict-free uint4 reads

    int ntile = blockIdx.x, ctile = blockIdx.y, bz = blockIdx.z;
    int b = bz / 3, m = bz % 3;
    const float* W  = (m == 0) ? Wq : ((m == 1) ? Wk : Wv);
    const float* eb = emb + (size_t)((m == 0) ? (BB + b) : b) * NN * EE;
    int n0 = ntile * 64, c0 = ctile * 64;
    int t = threadIdx.x;

    if (ntile == 0 && ctile == 0 && bz == 0 && t < BB) {
        g_sum[t] = 0.f; g_sumsq[t] = 0.f;
    }

    #pragma unroll
    for (int r = 0; r < 4; r++) {
        int chunk = t + 256 * r;
        int row = chunk >> 4;
        int col = (chunk & 15) * 4;
        *(float4*)&embS[row][col] = *(const float4*)&eb[(size_t)(n0 + row) * EE + col];
        *(float4*)&WS[row][col]   = *(const float4*)&W[(size_t)(c0 + row) * EE + col];
    }
    __syncthreads();

    int ty = t >> 4, tx = t & 15;
    float acc[4][4] = {};
    #pragma unroll 16
    for (int e = 0; e < 64; e++) {
        float a[4], bv[4];
        #pragma unroll
        for (int i = 0; i < 4; i++) a[i]  = embS[ty + 16 * i][e];
        #pragma unroll
        for (int j = 0; j < 4; j++) bv[j] = WS[tx + 16 * j][e];
        #pragma unroll
        for (int i = 0; i < 4; i++)
            #pragma unroll
            for (int j = 0; j < 4; j++) acc[i][j] += a[i] * bv[j];
    }

    if (m == 2) {
        #pragma unroll
        for (int i = 0; i < 4; i++)
            #pragma unroll
            for (int j = 0; j < 4; j++)
                g_vh[n0 + ty + 16 * i][b * CC + c0 + tx + 16 * j] = __float2half_rn(acc[i][j]);
        return;
    }

    // transpose via smem: transS[c_local][n_local]
    #pragma unroll
    for (int i = 0; i < 4; i++)
        #pragma unroll
        for (int j = 0; j < 4; j++)
            transS[tx + 16 * j][ty + 16 * i] = __float2half_rn(acc[i][j]);
    __syncthreads();

    int cl = t >> 2, g = t & 3;
    uint4 v0 = *(const uint4*)&transS[cl][g * 16];
    uint4 v1 = *(const uint4*)&transS[cl][g * 16 + 8];
    __half* dst = (m == 0) ? &g_qTh[b][c0 + cl][n0 + g * 16]
                           : &g_kTh[b * CC + c0 + cl][n0 + g * 16];
    *(uint4*)dst = v0;
    *(uint4*)(dst + 8) = v1;
}

// ---------------- kernel 2: scores GEMM (fp16 mma, round-8 verbatim) -------
__global__ __launch_bounds__(256, 2) void k_scores()
{
    __shared__ __align__(16) __half As[2][128 * 40];
    __shared__ __align__(16) __half Bs[2][128 * 40];
    __shared__ float red[256];

    const int m0 = blockIdx.x * 128, n0 = blockIdx.y * 128, b = blockIdx.z;
    const int t = threadIdx.x, lane = t & 31, warp = t >> 5;
    const int wm = (warp & 1) * 64, wn = (warp >> 1) * 32;

    const __half* A  = &g_qTh[b][m0][0];
    const __half* Bp = &g_kTh[n0][0];

    const int row0 = t >> 2;
    const int c16  = t & 3;

    uint4 fa[2], fb[2];
    auto ldg = [&](int k0) {
        #pragma unroll
        for (int r = 0; r < 2; r++) {
            int row = row0 + 64 * r;
            fa[r] = *(const uint4*)(A  + (size_t)row * NN + k0 + c16 * 8);
            fb[r] = *(const uint4*)(Bp + (size_t)row * NN + k0 + c16 * 8);
        }
    };
    auto sts = [&](int buf) {
        #pragma unroll
        for (int r = 0; r < 2; r++) {
            int row = row0 + 64 * r;
            *(uint4*)((char*)&As[buf][0] + row * 80 + c16 * 16) = fa[r];
            *(uint4*)((char*)&Bs[buf][0] + row * 80 + c16 * 16) = fb[r];
        }
    };

    float acc[4][4][4] = {};
    constexpr int T = NN / 32;
    ldg(0);

    for (int it = 0; it < T; it++) {
        int cur = it & 1;
        sts(cur);
        if (it + 1 < T) ldg((it + 1) * 32);
        __syncthreads();

        const __half* A_ = As[cur];
        const __half* B_ = Bs[cur];
        #pragma unroll
        for (int ks = 0; ks < 32; ks += 16) {
            int kk = ks + (lane & 3) * 2;
            uint32_t af[4][4], bf[4][2];
            #pragma unroll
            for (int mi = 0; mi < 4; mi++) {
                int m = wm + mi * 16 + (lane >> 2);
                af[mi][0] = lds32(A_, m,     kk);
                af[mi][1] = lds32(A_, m + 8, kk);
                af[mi][2] = lds32(A_, m,     kk + 8);
                af[mi][3] = lds32(A_, m + 8, kk + 8);
            }
            #pragma unroll
            for (int ni = 0; ni < 4; ni++) {
                int n = wn + ni * 8 + (lane >> 2);
                bf[ni][0] = lds32(B_, n, kk);
                bf[ni][1] = lds32(B_, n, kk + 8);
            }
            #pragma unroll
            for (int mi = 0; mi < 4; mi++)
                #pragma unroll
                for (int ni = 0; ni < 4; ni++)
                    mma_f16(acc[mi][ni], af[mi][0], af[mi][1], af[mi][2], af[mi][3],
                            bf[ni][0], bf[ni][1]);
        }
    }

    float ls = 0.f, lq = 0.f;
    #pragma unroll
    for (int mi = 0; mi < 4; mi++)
        #pragma unroll
        for (int ni = 0; ni < 4; ni++)
            #pragma unroll
            for (int h = 0; h < 2; h++) {
                int row = m0 + wm + mi * 16 + (lane >> 2) + h * 8;
                int col = n0 + wn + ni * 8 + 2 * (lane & 3);
                float v0 = acc[mi][ni][2 * h + 0];
                float v1 = acc[mi][ni][2 * h + 1];
                float2 st; st.x = v0; st.y = v1;
                *(float2*)&g_scores[b][row][col] = st;
                ls += v0 + v1;
                lq += v0 * v0 + v1 * v1;
            }

    __syncthreads();
    red[t] = ls; __syncthreads();
    for (int s = 128; s > 0; s >>= 1) { if (t < s) red[t] += red[t + s]; __syncthreads(); }
    if (t == 0) atomicAdd(&g_sum[b], red[0]);
    __syncthreads();
    red[t] = lq; __syncthreads();
    for (int s = 128; s > 0; s >>= 1) { if (t < s) red[t] += red[t + s]; __syncthreads(); }
    if (t == 0) atomicAdd(&g_sumsq[b], red[0]);
}

// ---------------- kernel 3: LN + exp -> half + row-sum (round-8 verbatim) --
__global__ __launch_bounds__(256) void k_softmax()
{
    int c = blockIdx.x, b = blockIdx.y;
    int t = threadIdx.x;
    __shared__ float red[256];

    const float invCD = 1.0f / ((float)CC * (float)DD);
    float mean = g_sum[b] * invCD;
    float var  = g_sumsq[b] * invCD - mean * mean;
    float rstd = rsqrtf(var + EPS_LN);

    const float* row = &g_scores[b][c][0];
    __half* erow = &g_expS[b][c][0];
    float ls = 0.f;
    #pragma unroll
    for (int r = 0; r < 4; r++) {
        int idx = (t + 256 * r) * 4;
        float4 v = *(const float4*)&row[idx];
        v.x = __expf((v.x - mean) * rstd);
        v.y = __expf((v.y - mean) * rstd);
        v.z = __expf((v.z - mean) * rstd);
        v.w = __expf((v.w - mean) * rstd);
        ls += v.x + v.y + v.z + v.w;
        __half2 h0 = __floats2half2_rn(v.x, v.y);
        __half2 h1 = __floats2half2_rn(v.z, v.w);
        __half2* dst = (__half2*)&erow[idx];
        dst[0] = h0; dst[1] = h1;
    }
    red[t] = ls; __syncthreads();
    for (int s = 128; s > 0; s >>= 1) { if (t < s) red[t] += red[t + s]; __syncthreads(); }
    if (t == 0) g_rowinv[b][c] = 1.0f / red[0];
}

// ---------------- kernel 4: ctx GEMM (fp16 mma, round-8 verbatim) ----------
__global__ __launch_bounds__(256, 2) void k_ctx()
{
    __shared__ __align__(16) __half As[2][128 * 40];
    __shared__ __align__(16) __half Bs[2][128 * 40];

    const int m0 = blockIdx.x * 128, n0 = blockIdx.y * 128, b = blockIdx.z;
    const int t = threadIdx.x, lane = t & 31, warp = t >> 5;
    const int wm = (warp & 1) * 64, wn = (warp >> 1) * 32;

    const __half* A  = &g_expS[b][m0][0];
    const __half* Bp = &g_vh[n0][0];

    const int row0 = t >> 2;
    const int c16  = t & 3;

    uint4 fa[2], fb[2];
    auto ldg = [&](int k0) {
        #pragma unroll
        for (int r = 0; r < 2; r++) {
            int row = row0 + 64 * r;
            fa[r] = *(const uint4*)(A  + (size_t)row * DD + k0 + c16 * 8);
            fb[r] = *(const uint4*)(Bp + (size_t)row * DD + k0 + c16 * 8);
        }
    };
    auto sts = [&](int buf) {
        #pragma unroll
        for (int r = 0; r < 2; r++) {
            int row = row0 + 64 * r;
            *(uint4*)((char*)&As[buf][0] + row * 80 + c16 * 16) = fa[r];
            *(uint4*)((char*)&Bs[buf][0] + row * 80 + c16 * 16) = fb[r];
        }
    };

    float acc[4][4][4] = {};
    constexpr int T = DD / 32;
    ldg(0);

    for (int it = 0; it < T; it++) {
        int cur = it & 1;
        sts(cur);
        if (it + 1 < T) ldg((it + 1) * 32);
        __syncthreads();

        const __half* A_ = As[cur];
        const __half* B_ = Bs[cur];
        #pragma unroll
        for (int ks = 0; ks < 32; ks += 16) {
            int kk = ks + (lane & 3) * 2;
            uint32_t af[4][4], bf[4][2];
            #pragma unroll
            for (int mi = 0; mi < 4; mi++) {
                int m = wm + mi * 16 + (lane >> 2);
                af[mi][0] = lds32(A_, m,     kk);
                af[mi][1] = lds32(A_, m + 8, kk);
                af[mi][2] = lds32(A_, m,     kk + 8);
                af[mi][3] = lds32(A_, m + 8, kk + 8);
            }
            #pragma unroll
            for (int ni = 0; ni < 4; ni++) {
                int n = wn + ni * 8 + (lane >> 2);
                bf[ni][0] = lds32(B_, n, kk);
                bf[ni][1] = lds32(B_, n, kk + 8);
            }
            #pragma unroll
            for (int mi = 0; mi < 4; mi++)
                #pragma unroll
                for (int ni = 0; ni < 4; ni++)
                    mma_f16(acc[mi][ni], af[mi][0], af[mi][1], af[mi][2], af[mi][3],
                            bf[ni][0], bf[ni][1]);
        }
    }

    #pragma unroll
    for (int mi = 0; mi < 4; mi++)
        #pragma unroll
        for (int ni = 0; ni < 4; ni++)
            #pragma unroll
            for (int h = 0; h < 2; h++) {
                int row = m0 + wm + mi * 16 + (lane >> 2) + h * 8;
                int col = n0 + wn + ni * 8 + 2 * (lane & 3);
                float inv = g_rowinv[b][row];
                float2 st;
                st.x = acc[mi][ni][2 * h + 0] * inv;
                st.y = acc[mi][ni][2 * h + 1] * inv;
                *(float2*)&g_ctx[b][row][col] = st;
            }
}

// ---------------- kernel 5: output projection (tf32 mma) --------------------
// out[b][n][e] = sum_c ctx[b][c][n] * Wo[e][c].  GEMM: M=64(e) x N=128(n),
// K=512(c). A = Wo (k-contig rows), B = g_ctx[c][n] loaded in natural layout
// (tf32 frags are 1 elem/reg -> no transpose needed).
__global__ __launch_bounds__(256) void k_out(
    const float* __restrict__ Wo, float* __restrict__ out)
{
    __shared__ float As[2][64 * 20];     // [e][k], stride 20 words
    __shared__ float Bs[2][16 * 136];    // [c][n], stride 136 words (8k+n banks)

    const int n0 = blockIdx.x * 128;
    const int b  = blockIdx.y;
    const int t = threadIdx.x, lane = t & 31, warp = t >> 5;
    const int wn = warp * 16;            // 8 warps x 16 n

    const int a_e = t >> 2,  a_k  = (t & 3) * 4;   // A: 64x16 floats, 1 float4/thr
    const int b_cc = t >> 5, b_nn = (t & 31) * 4;  // B: 16x128 floats, 2 float4/thr

    float4 fa, fb0, fb1;
    auto ldg = [&](int c0) {
        fa  = *(const float4*)&Wo[(size_t)a_e * CC + c0 + a_k];
        fb0 = *(const float4*)&g_ctx[b][c0 + b_cc][n0 + b_nn];
        fb1 = *(const float4*)&g_ctx[b][c0 + b_cc + 8][n0 + b_nn];
    };
    auto sts = [&](int buf) {
        float4 ca;
        ca.x = tf32f(fa.x); ca.y = tf32f(fa.y); ca.z = tf32f(fa.z); ca.w = tf32f(fa.w);
        *(float4*)&As[buf][a_e * 20 + a_k] = ca;
        float4 c0v, c1v;
        c0v.x = tf32f(fb0.x); c0v.y = tf32f(fb0.y); c0v.z = tf32f(fb0.z); c0v.w = tf32f(fb0.w);
        c1v.x = tf32f(fb1.x); c1v.y = tf32f(fb1.y); c1v.z = tf32f(fb1.z); c1v.w = tf32f(fb1.w);
        *(float4*)&Bs[buf][b_cc * 136 + b_nn] = c0v;
        *(float4*)&Bs[buf][(b_cc + 8) * 136 + b_nn] = c1v;
    };

    float acc[4][2][4] = {};
    constexpr int T = CC / 16;
    ldg(0);

    for (int it = 0; it < T; it++) {
        int cur = it & 1;
        sts(cur);
        if (it + 1 < T) ldg((it + 1) * 16);
        __syncthreads();

        const float* A_ = As[cur];
        const float* B_ = Bs[cur];
        #pragma unroll
        for (int ks = 0; ks < 16; ks += 8) {
            int kk = ks + (lane & 3);
            uint32_t af[4][4], bf[2][2];
            #pragma unroll
            for (int mi = 0; mi < 4; mi++) {
                int m = mi * 16 + (lane >> 2);
                af[mi][0] = __float_as_uint(A_[m * 20 + kk]);
                af[mi][1] = __float_as_uint(A_[(m + 8) * 20 + kk]);
                af[mi][2] = __float_as_uint(A_[m * 20 + kk + 4]);
                af[mi][3] = __float_as_uint(A_[(m + 8) * 20 + kk + 4]);
            }
            #pragma unroll
            for (int ni = 0; ni < 2; ni++) {
                int n = wn + ni * 8 + (lane >> 2);
                bf[ni][0] = __float_as_uint(B_[kk * 136 + n]);
                bf[ni][1] = __float_as_uint(B_[(kk + 4) * 136 + n]);
            }
            #pragma unroll
            for (int mi = 0; mi < 4; mi++)
                #pragma unroll
                for (int ni = 0; ni < 2; ni++)
                    mma_tf32(acc[mi][ni], af[mi][0], af[mi][1], af[mi][2], af[mi][3],
                             bf[ni][0], bf[ni][1]);
        }
    }

    // epilogue: acc row = e, col = n (within tile)
    #pragma unroll
    for (int mi = 0; mi < 4; mi++)
        #pragma unroll
        for (int ni = 0; ni < 2; ni++)
            #pragma unroll
            for (int h = 0; h < 2; h++) {
                int e = mi * 16 + (lane >> 2) + h * 8;
                int n = n0 + wn + ni * 8 + 2 * (lane & 3);
                out[((size_t)b * NN + n) * EE + e]       = acc[mi][ni][2 * h + 0];
                out[((size_t)b * NN + n + 1) * EE + e]   = acc[mi][ni][2 * h + 1];
            }
}

// ---------------- launch ---------------------------------------------------
extern "C" void kernel_launch(void* const* d_in, const int* in_sizes, int n_in,
                              void* d_out, int out_size)
{
    const float* emb = (const float*)d_in[0];
    const float* Wq  = (const float*)d_in[1];
    const float* Wk  = (const float*)d_in[2];
    const float* Wv  = (const float*)d_in[3];
    const float* Wo  = (const float*)d_in[4];
    float* out = (float*)d_out;

    dim3 g1(16, 8, 24);
    k_proj<<<g1, 256>>>(emb, Wq, Wk, Wv);

    dim3 g2(CC / 128, DD / 128, BB);     // 4 x 32 x 8
    k_scores<<<g2, 256>>>();

    dim3 g3(512, 8);
    k_softmax<<<g3, 256>>>();

    dim3 g4(CC / 128, NN / 128, BB);     // 4 x 8 x 8
    k_ctx<<<g4, 256>>>();

    dim3 g5(NN / 128, BB);               // 8 x 8
    k_out<<<g5, 256>>>(Wo, out);
}